// round 3
// baseline (speedup 1.0000x reference)
#include <cuda_runtime.h>
#include <math.h>

#define BB 8
#define SS 4
#define NN 8192
#define MM 50
#define BSN (BB*SS*NN)   // 262144
#define INF_F 3.4e38f

// ---------------- scratch (no allocations allowed) ----------------
__device__ float    g_px[BSN];
__device__ float    g_py[BSN];
__device__ float    g_pz[BSN];
__device__ int      g_assign[BSN];
__device__ unsigned g_flag[BB*SS];
// 0: center_sum, 1: n_pos, 2: sum_pos softplus(-x), 3: sum_neg softplus(x), 4: sum_unmatched
__device__ double   g_acc[5];

// ---------------- transpose + init (1 launch, 4 boxes/thread for MLP) ----------------
__global__ void prep_kernel(const float* __restrict__ pb) {
    const int t  = blockIdx.x * blockDim.x + threadIdx.x;
    const int i0 = t * 4;
    // issue all 12 loads before any store (MLP=12)
    float x0 = pb[(size_t)(i0+0)*7+0], y0 = pb[(size_t)(i0+0)*7+1], z0 = pb[(size_t)(i0+0)*7+2];
    float x1 = pb[(size_t)(i0+1)*7+0], y1 = pb[(size_t)(i0+1)*7+1], z1 = pb[(size_t)(i0+1)*7+2];
    float x2 = pb[(size_t)(i0+2)*7+0], y2 = pb[(size_t)(i0+2)*7+1], z2 = pb[(size_t)(i0+2)*7+2];
    float x3 = pb[(size_t)(i0+3)*7+0], y3 = pb[(size_t)(i0+3)*7+1], z3 = pb[(size_t)(i0+3)*7+2];
    g_px[i0+0]=x0; g_py[i0+0]=y0; g_pz[i0+0]=z0; g_assign[i0+0]=-1;
    g_px[i0+1]=x1; g_py[i0+1]=y1; g_pz[i0+1]=z1; g_assign[i0+1]=-1;
    g_px[i0+2]=x2; g_py[i0+2]=y2; g_pz[i0+2]=z2; g_assign[i0+2]=-1;
    g_px[i0+3]=x3; g_py[i0+3]=y3; g_pz[i0+3]=z3; g_assign[i0+3]=-1;
    if (t < BB*SS) g_flag[t] = 0u;
    if (t < 5)     g_acc[t]  = 0.0;
}

// lexicographic (val, idx) warp min -> valid on lane 0
__device__ __forceinline__ void warp_min(float& v, int& i) {
    #pragma unroll
    for (int off = 16; off; off >>= 1) {
        float ov = __shfl_down_sync(0xffffffffu, v, off);
        int   oi = __shfl_down_sync(0xffffffffu, i, off);
        if (ov < v || (ov == v && oi < i)) { v = ov; i = oi; }
    }
}

// ---------------- per-(b,s,4-gt-group) top-10 selection ----------------
// One 256-thread block per (b, s, group-of-4 gts). Coordinates for the whole
// (b,s) slice are loaded ONCE into registers (32 elems/thread = 96 regs),
// then two sub-rounds each compute distances for a gt pair into 64 KB of
// smem (with fused 64x128-segment minima) and run 10 selection rounds
// (warp 0 -> first gt, warp 1 -> second gt of the pair).
__global__ void __launch_bounds__(256, 2)
topk_kernel(const float* __restrict__ gtb,
            const int*   __restrict__ n_gt,
            const float* __restrict__ scores) {
    extern __shared__ float smem[];
    float* sd0 = smem;            // [8192]
    float* sd1 = smem + NN;       // [8192]
    __shared__ float segv[2][64];
    __shared__ int   segi[2][64];

    const int mp = blockIdx.x, s = blockIdx.y, b = blockIdx.z;
    const int mbase = mp * 4;
    const int ngt = n_gt[b];
    if (mbase >= ngt) return;

    const int tid  = threadIdx.x;
    const int w    = tid >> 5;           // 0..7, warp covers [w*1024,(w+1)*1024)
    const int lane = tid & 31;
    const int gbase = (b*SS + s) * NN;

    // gt coords for the 4 gts (clamped loads to stay in-bounds; selection gated later)
    float gx[4], gy[4], gz[4];
    #pragma unroll
    for (int j = 0; j < 4; ++j) {
        int m = mbase + j; if (m > MM-1) m = MM-1;
        gx[j] = gtb[(b*MM + m)*7 + 0];
        gy[j] = gtb[(b*MM + m)*7 + 1];
        gz[j] = gtb[(b*MM + m)*7 + 2];
    }

    // ---- load coordinates into registers (once) ----
    float cx[32], cy[32], cz[32];
    #pragma unroll
    for (int i = 0; i < 32; ++i) {
        const int e = w*1024 + i*32 + lane;
        cx[i] = g_px[gbase + e];
        cy[i] = g_py[gbase + e];
        cz[i] = g_pz[gbase + e];
    }

    #pragma unroll
    for (int r = 0; r < 2; ++r) {
        const int ma = mbase + 2*r;      // gt for warp 0
        const int mb = ma + 1;           // gt for warp 1
        if (ma >= ngt) return;           // uniform: later gts also invalid

        // ---- phase 1: distances + fused segment minima ----
        {
            const float ax = gx[2*r], ay = gy[2*r], az = gz[2*r];
            const float bx = gx[2*r+1], by = gy[2*r+1], bz = gz[2*r+1];
            float rv0 = INF_F, rv1 = INF_F;
            int   ri0 = 0,     ri1 = 0;
            #pragma unroll
            for (int i = 0; i < 32; ++i) {
                const int e = w*1024 + i*32 + lane;
                float dx = cx[i] - ax, dy = cy[i] - ay, dz = cz[i] - az;
                const float d0 = fmaf(dx, dx, fmaf(dy, dy, dz*dz));
                dx = cx[i] - bx; dy = cy[i] - by; dz = cz[i] - bz;
                const float d1 = fmaf(dx, dx, fmaf(dy, dy, dz*dz));
                sd0[e] = d0;
                sd1[e] = d1;
                if (d0 < rv0) { rv0 = d0; ri0 = e; }
                if (d1 < rv1) { rv1 = d1; ri1 = e; }
                if ((i & 3) == 3) {
                    float tv0 = rv0; int ti0 = ri0;
                    float tv1 = rv1; int ti1 = ri1;
                    warp_min(tv0, ti0);
                    warp_min(tv1, ti1);
                    if (lane == 0) {
                        const int sg = w*8 + (i >> 2);
                        segv[0][sg] = tv0; segi[0][sg] = ti0;
                        segv[1][sg] = tv1; segi[1][sg] = ti1;
                    }
                    rv0 = INF_F; rv1 = INF_F; ri0 = 0; ri1 = 0;
                }
            }
        }
        __syncthreads();

        // ---- phase 2: 10 selection rounds (warp 0 -> ma, warp 1 -> mb) ----
        if (w < 2 && !(w == 1 && mb >= ngt)) {
            float* sd  = (w == 0) ? sd0 : sd1;
            float* sgv = segv[w];
            int*   sgi = segi[w];

            float topv[10];
            int   topi[10];
            #pragma unroll
            for (int it = 0; it < 10; ++it) {
                float v  = sgv[lane];      int ei  = sgi[lane];
                float v2 = sgv[lane + 32]; int ei2 = sgi[lane + 32];
                if (v2 < v || (v2 == v && ei2 < ei)) { v = v2; ei = ei2; }
                warp_min(v, ei);
                v  = __shfl_sync(0xffffffffu, v,  0);
                ei = __shfl_sync(0xffffffffu, ei, 0);
                topv[it] = v; topi[it] = ei;
                const int sg = ei >> 7;
                if (lane == 0) sd[ei] = INF_F;
                __syncwarp();
                const int rb = sg*128 + lane*4;
                float nv = INF_F; int ni = rb;
                #pragma unroll
                for (int j = 0; j < 4; ++j) {
                    const float t = sd[rb + j];
                    if (t < nv) { nv = t; ni = rb + j; }
                }
                warp_min(nv, ni);
                if (lane == 0) { sgv[sg] = nv; sgi[sg] = ni; }
                __syncwarp();
            }

            if (lane == 0) {
                const int mm = (w == 0) ? ma : mb;
                bool matched = false;
                #pragma unroll
                for (int j = 0; j < 10; ++j) {
                    if (sqrtf(topv[j]) < 50.0f) {
                        atomicMax(&g_assign[gbase + topi[j]], mm);
                        matched = true;
                    }
                }
                if (!matched) {
                    float pg = 0.f;
                    #pragma unroll
                    for (int j = 0; j < 5; ++j)
                        pg += expf(-sqrtf(topv[j]) * 0.5f) * (1.0f - scores[gbase + topi[j]]);
                    atomicAdd(&g_acc[4], (double)(pg * 0.2f));
                    atomicOr(&g_flag[b*SS + s], 1u);
                }
            }
        }
        __syncthreads();   // selection done before next sub-round overwrites smem
    }
}

// ---------------- fused reduction + final combine (last block) ----------------
__device__ unsigned g_done;
__global__ void reduce_kernel(const float* __restrict__ scores,
                              const float* __restrict__ gtb,
                              float* __restrict__ out,
                              const float* __restrict__ wc,
                              const float* __restrict__ wo,
                              const float* __restrict__ wu) {
    const int gid = blockIdx.x * blockDim.x + threadIdx.x;
    const int stride = gridDim.x * blockDim.x;

    double c_sum = 0.0, sp1 = 0.0, sp2 = 0.0, np = 0.0;

    for (int i = gid; i < BSN; i += stride) {
        const int a = g_assign[i];
        const float x = scores[i];
        const float l1p = log1pf(expf(-fabsf(x)));   // shared tail of softplus(+-x)
        if (a >= 0) {
            np  += 1.0;
            sp1 += (double)(fmaxf(-x, 0.f) + l1p);    // softplus(-x)
            const int bb = i >> 15;                   // / (S*N)
            const float* g = gtb + (size_t)(bb*MM + a) * 7;
            float dd, ad;
            dd = g_px[i] - g[0]; ad = fabsf(dd);
            c_sum += (double)((ad < 1.f) ? 0.5f*ad*ad : ad - 0.5f);
            dd = g_py[i] - g[1]; ad = fabsf(dd);
            c_sum += (double)((ad < 1.f) ? 0.5f*ad*ad : ad - 0.5f);
            dd = g_pz[i] - g[2]; ad = fabsf(dd);
            c_sum += (double)((ad < 1.f) ? 0.5f*ad*ad : ad - 0.5f);
        } else {
            sp2 += (double)(fmaxf(x, 0.f) + l1p);     // softplus(x)
        }
    }

    #pragma unroll
    for (int off = 16; off; off >>= 1) {
        c_sum += __shfl_down_sync(0xffffffffu, c_sum, off);
        sp1   += __shfl_down_sync(0xffffffffu, sp1,   off);
        sp2   += __shfl_down_sync(0xffffffffu, sp2,   off);
        np    += __shfl_down_sync(0xffffffffu, np,    off);
    }
    __shared__ double sm[4][8];
    const int w = threadIdx.x >> 5;
    if ((threadIdx.x & 31) == 0) { sm[0][w]=c_sum; sm[1][w]=sp1; sm[2][w]=sp2; sm[3][w]=np; }
    __syncthreads();
    if (threadIdx.x == 0) {
        #pragma unroll
        for (int k = 1; k < 8; ++k) { c_sum+=sm[0][k]; sp1+=sm[1][k]; sp2+=sm[2][k]; np+=sm[3][k]; }
        atomicAdd(&g_acc[0], c_sum);
        atomicAdd(&g_acc[1], np);
        atomicAdd(&g_acc[2], sp1);
        atomicAdd(&g_acc[3], sp2);
        __threadfence();
        const unsigned t = atomicAdd(&g_done, 1u);
        if (t == gridDim.x - 1) {
            g_done = 0u;   // reset for next graph replay
            const double npos = g_acc[1];
            const double loss_center = g_acc[0] / fmax(npos * 3.0, 1.0);
            const double nneg = (double)BSN - npos;
            const double pw = fmin(10.0, nneg / fmax(npos, 1.0));
            const double loss_obj = (pw * g_acc[2] + g_acc[3]) / (double)BSN;
            int ne = 0;
            #pragma unroll
            for (int k = 0; k < BB*SS; ++k) ne += (g_flag[k] ? 1 : 0);
            const double loss_unm = g_acc[4] / fmax((double)ne, 1.0);
            out[0] = (float)(loss_center * (double)wc[0] +
                             loss_obj    * (double)wo[0] +
                             loss_unm    * (double)wu[0]);
        }
    }
}

// ---------------- launch ----------------
extern "C" void kernel_launch(void* const* d_in, const int* in_sizes, int n_in,
                              void* d_out, int out_size) {
    const float* pb     = (const float*)d_in[0];   // pred_boxes  [8,4,8192,7]
    const float* scores = (const float*)d_in[2];   // pred_scores [8,4,8192]
    const float* gtb    = (const float*)d_in[3];   // gt_boxes    [8,50,7]
    const int*   n_gt   = (const int*)d_in[5];     // [8]
    const float* wc     = (const float*)d_in[6];
    const float* wo     = (const float*)d_in[7];
    const float* wu     = (const float*)d_in[8];
    float* out = (float*)d_out;

    cudaFuncSetAttribute(topk_kernel,
                         cudaFuncAttributeMaxDynamicSharedMemorySize,
                         2 * NN * sizeof(float));

    prep_kernel<<<BSN / (256*4), 256>>>(pb);
    dim3 grid((MM + 3) / 4, SS, BB);   // 13 x 4 x 8 = 416 blocks
    topk_kernel<<<grid, 256, 2 * NN * sizeof(float)>>>(gtb, n_gt, scores);
    reduce_kernel<<<148, 256>>>(scores, gtb, out, wc, wo, wu);
}